// round 3
// baseline (speedup 1.0000x reference)
#include <cuda_runtime.h>

// Problem constants
#define BSZ 2
#define NSEQ 2048
#define DIMM 256
#define HH 8
#define DHD 32
#define M_TOT (BSZ*NSEQ)          // 4096
#define KK1 512
#define NN1 1536
#define NN2 512
#define REGSTRIDE (BSZ*HH*NSEQ*DHD)   // 1048576 floats per region

// ---------------- scratch (device globals; no runtime allocation) -------------
__device__ __align__(16) float g_W1[KK1*NN1];      // packed QKV weights  (3 MB)
__device__ __align__(16) float g_W2[KK1*NN2];      // packed output weights (1 MB)
__device__ __align__(16) float g_QKV[6*REGSTRIDE]; // qr,qi,kr,ki,vr,vi head-split (24 MB)
__device__ __align__(16) float g_Mr[M_TOT*DIMM];   // merged attention out real (4 MB)
__device__ __align__(16) float g_Mi[M_TOT*DIMM];   // merged attention out imag (4 MB)

// ---------------- weight packing ---------------------------------------------
// W1 columns: [qr | qi | kr | ki | vr | vi], rows: [xr-side(256) ; xi-side(256)]
__global__ void pack_w1(const float* __restrict__ wq_r, const float* __restrict__ wq_i,
                        const float* __restrict__ wkv_r, const float* __restrict__ wkv_i) {
    int idx = blockIdx.x*blockDim.x + threadIdx.x;
    if (idx >= KK1*NN1) return;
    int k = idx / NN1, c = idx % NN1;
    int reg = c >> 8, cc = c & 255;
    bool top = (k < 256);
    int kr = k & 255;
    float v;
    switch (reg) {
        case 0: v = top ? wq_r[kr*256+cc]       : -wq_i[kr*256+cc];       break; // qr
        case 1: v = top ? wq_i[kr*256+cc]       :  wq_r[kr*256+cc];       break; // qi
        case 2: v = top ? wkv_r[kr*512+cc]      : -wkv_i[kr*512+cc];      break; // kr
        case 3: v = top ? wkv_i[kr*512+cc]      :  wkv_r[kr*512+cc];      break; // ki
        case 4: v = top ? wkv_r[kr*512+256+cc]  : -wkv_i[kr*512+256+cc];  break; // vr
        default:v = top ? wkv_i[kr*512+256+cc]  :  wkv_r[kr*512+256+cc];  break; // vi
    }
    g_W1[idx] = v;
}

// W2 columns: [out_r(256) | out_i(256)], rows: [mr-side(256) ; mi-side(256)]
__global__ void pack_w2(const float* __restrict__ wo_r, const float* __restrict__ wo_i) {
    int idx = blockIdx.x*blockDim.x + threadIdx.x;
    if (idx >= KK1*NN2) return;
    int k = idx / NN2, c = idx % NN2;
    bool top = (k < 256);
    int kr = k & 255;
    int co = c & 255;
    float v;
    if (c < 256) v = top ? wo_r[kr*256+co] : -wo_i[kr*256+co];
    else         v = top ? wo_i[kr*256+co] :  wo_r[kr*256+co];
    g_W2[idx] = v;
}

// ---------------- GEMM 1: X[4096,512] @ W1[512,1536] -> head-split QKV --------
__global__ void gemm_qkv(const float* __restrict__ xr, const float* __restrict__ xi) {
    __shared__ __align__(16) float As[16][64];
    __shared__ __align__(16) float Bs[16][64];
    int tid = threadIdx.x;
    int tx = tid & 15, ty = tid >> 4;
    int mBase = blockIdx.y * 64;
    int nBase = blockIdx.x * 64;
    float acc[4][4] = {};
    for (int kt = 0; kt < KK1; kt += 16) {
        {
            int lin = tid * 4;
            int ar = lin >> 4, ak = lin & 15;
            int gm = mBase + ar, gk = kt + ak;
            const float* src = (gk < 256) ? (xr + (size_t)gm*256 + gk)
                                          : (xi + (size_t)gm*256 + gk - 256);
            float4 v = *(const float4*)src;
            As[ak+0][ar] = v.x; As[ak+1][ar] = v.y; As[ak+2][ar] = v.z; As[ak+3][ar] = v.w;
        }
        {
            int lin = tid * 4;
            int bk = lin >> 6, bc = lin & 63;
            *(float4*)&Bs[bk][bc] = *(const float4*)&g_W1[(size_t)(kt+bk)*NN1 + nBase + bc];
        }
        __syncthreads();
        #pragma unroll
        for (int k = 0; k < 16; k++) {
            float a[4], bb[4];
            #pragma unroll
            for (int i = 0; i < 4; i++) a[i] = As[k][ty*4+i];
            #pragma unroll
            for (int j = 0; j < 4; j++) bb[j] = Bs[k][tx*4+j];
            #pragma unroll
            for (int i = 0; i < 4; i++)
                #pragma unroll
                for (int j = 0; j < 4; j++) acc[i][j] += a[i]*bb[j];
        }
        __syncthreads();
    }
    #pragma unroll
    for (int i = 0; i < 4; i++) {
        int m = mBase + ty*4 + i;
        int b = m >> 11, n = m & 2047;
        #pragma unroll
        for (int j = 0; j < 4; j++) {
            int c = nBase + tx*4 + j;
            int reg = c >> 8, rem = c & 255;
            int h = rem >> 5, d = rem & 31;
            g_QKV[((size_t)(reg*BSZ*HH) + (size_t)(b*HH + h))*NSEQ*DHD + (size_t)n*DHD + d] = acc[i][j];
        }
    }
}

// ---------------- fused 4-replica flash attention ----------------------------
struct AtSmem {
    float qr[32][36];
    float qi[32][36];
    float kr[64][36];
    float ki[64][36];
    float vr[64][36];
    float vi[64][36];
    float p[4][32][72];
};

__global__ void attn_kernel() {
    extern __shared__ unsigned char smraw[];
    AtSmem& S = *reinterpret_cast<AtSmem*>(smraw);
    const int bh = blockIdx.x;                 // 0..15
    const int b = bh >> 3, h = bh & 7;
    const int row0 = blockIdx.y * 32;          // 64 row-tiles
    const int tid = threadIdx.x;               // 256 threads
    const int r = tid >> 3;                    // row within tile 0..31
    const int g = tid & 7;                     // col/dim group 0..7

    const size_t base = ((size_t)(b*HH + h)) * NSEQ * DHD;
    const float* Qr = g_QKV + 0*(size_t)REGSTRIDE + base;
    const float* Qi = g_QKV + 1*(size_t)REGSTRIDE + base;
    const float* Kr = g_QKV + 2*(size_t)REGSTRIDE + base;
    const float* Ki = g_QKV + 3*(size_t)REGSTRIDE + base;
    const float* Vr = g_QKV + 4*(size_t)REGSTRIDE + base;
    const float* Vi = g_QKV + 5*(size_t)REGSTRIDE + base;

    for (int i = tid; i < 32*32; i += 256) {
        int rr = i >> 5, dd = i & 31;
        S.qr[rr][dd] = Qr[(size_t)(row0+rr)*32 + dd];
        S.qi[rr][dd] = Qi[(size_t)(row0+rr)*32 + dd];
    }

    float m_run[4] = {-1e30f, -1e30f, -1e30f, -1e30f};
    float l_run[4] = {0.f, 0.f, 0.f, 0.f};
    float accr[4][4] = {};
    float acci[4][4] = {};
    const float scale = 0.17677669529663687f;   // 1/sqrt(32)

    for (int ct = 0; ct < NSEQ; ct += 64) {
        __syncthreads();
        for (int i = tid; i < 64*32; i += 256) {
            int rr = i >> 5, dd = i & 31;
            size_t gr = (size_t)(ct+rr)*32 + dd;
            S.kr[rr][dd] = Kr[gr];
            S.ki[rr][dd] = Ki[gr];
            S.vr[rr][dd] = Vr[gr];
            S.vi[rr][dd] = Vi[gr];
        }
        __syncthreads();

        // scores: 4 replicas x 8 columns per thread (cols j = g + 8t)
        float s[4][8];
        #pragma unroll
        for (int rep = 0; rep < 4; rep++)
            #pragma unroll
            for (int t = 0; t < 8; t++) s[rep][t] = 0.f;

        #pragma unroll
        for (int dc = 0; dc < 8; dc++) {
            float4 aR = *(const float4*)&S.qr[r][dc*4];
            float4 aI = *(const float4*)&S.qi[r][dc*4];
            #pragma unroll
            for (int t = 0; t < 8; t++) {
                int j = g + t*8;
                float4 kR = *(const float4*)&S.kr[j][dc*4];
                float4 kI = *(const float4*)&S.ki[j][dc*4];
                s[0][t] += aR.x*kR.x + aR.y*kR.y + aR.z*kR.z + aR.w*kR.w;
                s[1][t] += aR.x*kI.x + aR.y*kI.y + aR.z*kI.z + aR.w*kI.w;
                s[2][t] += aI.x*kR.x + aI.y*kR.y + aI.z*kR.z + aI.w*kR.w;
                s[3][t] += aI.x*kI.x + aI.y*kI.y + aI.z*kI.z + aI.w*kI.w;
            }
        }

        // online softmax per replica (row = 8 consecutive lanes in a warp)
        float alpha[4];
        #pragma unroll
        for (int rep = 0; rep < 4; rep++) {
            float mx = -1e30f;
            #pragma unroll
            for (int t = 0; t < 8; t++) { s[rep][t] *= scale; mx = fmaxf(mx, s[rep][t]); }
            #pragma unroll
            for (int o = 1; o < 8; o <<= 1) mx = fmaxf(mx, __shfl_xor_sync(0xffffffffu, mx, o));
            float mnew = fmaxf(m_run[rep], mx);
            alpha[rep] = __expf(m_run[rep] - mnew);
            m_run[rep] = mnew;
            float ps = 0.f;
            #pragma unroll
            for (int t = 0; t < 8; t++) {
                float p = __expf(s[rep][t] - mnew);
                S.p[rep][r][g + t*8] = p;
                ps += p;
            }
            #pragma unroll
            for (int o = 1; o < 8; o <<= 1) ps += __shfl_xor_sync(0xffffffffu, ps, o);
            l_run[rep] = l_run[rep]*alpha[rep] + ps;
        }

        #pragma unroll
        for (int rep = 0; rep < 4; rep++)
            #pragma unroll
            for (int dd = 0; dd < 4; dd++) { accr[rep][dd] *= alpha[rep]; acci[rep][dd] *= alpha[rep]; }

        __syncwarp();   // p written/read only within the row's 8 lanes (same warp)

        // A @ [vr, vi]: thread accumulates dims [4g, 4g+4) over all 64 columns
        #pragma unroll 4
        for (int j = 0; j < 64; j++) {
            float4 vR = *(const float4*)&S.vr[j][g*4];
            float4 vI = *(const float4*)&S.vi[j][g*4];
            #pragma unroll
            for (int rep = 0; rep < 4; rep++) {
                float p = S.p[rep][r][j];
                accr[rep][0] += p*vR.x; accr[rep][1] += p*vR.y;
                accr[rep][2] += p*vR.z; accr[rep][3] += p*vR.w;
                acci[rep][0] += p*vI.x; acci[rep][1] += p*vI.y;
                acci[rep][2] += p*vI.z; acci[rep][3] += p*vI.w;
            }
        }
    }

    // sign recombination:
    // o_r = A0 vr - A1 vi - A2 vi - A3 vr ;  o_i = A0 vi + A1 vr + A2 vr - A3 vi
    float n0 = 1.f/l_run[0], n1 = 1.f/l_run[1], n2 = 1.f/l_run[2], n3 = 1.f/l_run[3];
    int n = row0 + r;
    size_t midx = ((size_t)(b*NSEQ + n))*DIMM + h*DHD + g*4;
    #pragma unroll
    for (int dd = 0; dd < 4; dd++) {
        float orr = n0*accr[0][dd] - n1*acci[1][dd] - n2*acci[2][dd] - n3*accr[3][dd];
        float oii = n0*acci[0][dd] + n1*accr[1][dd] + n2*accr[2][dd] - n3*acci[3][dd];
        g_Mr[midx+dd] = orr;
        g_Mi[midx+dd] = oii;
    }
}

// ---------------- GEMM 2: [Mr|Mi][4096,512] @ W2[512,512] -> interleaved out --
__global__ void gemm_out(float* __restrict__ out) {
    __shared__ __align__(16) float As[16][64];
    __shared__ __align__(16) float Bs[16][64];
    int tid = threadIdx.x;
    int tx = tid & 15, ty = tid >> 4;
    int mBase = blockIdx.y * 64;
    int nBase = blockIdx.x * 64;
    float acc[4][4] = {};
    for (int kt = 0; kt < KK1; kt += 16) {
        {
            int lin = tid * 4;
            int ar = lin >> 4, ak = lin & 15;
            int gm = mBase + ar, gk = kt + ak;
            const float* src = (gk < 256) ? (g_Mr + (size_t)gm*256 + gk)
                                          : (g_Mi + (size_t)gm*256 + gk - 256);
            float4 v = *(const float4*)src;
            As[ak+0][ar] = v.x; As[ak+1][ar] = v.y; As[ak+2][ar] = v.z; As[ak+3][ar] = v.w;
        }
        {
            int lin = tid * 4;
            int bk = lin >> 6, bc = lin & 63;
            *(float4*)&Bs[bk][bc] = *(const float4*)&g_W2[(size_t)(kt+bk)*NN2 + nBase + bc];
        }
        __syncthreads();
        #pragma unroll
        for (int k = 0; k < 16; k++) {
            float a[4], bb[4];
            #pragma unroll
            for (int i = 0; i < 4; i++) a[i] = As[k][ty*4+i];
            #pragma unroll
            for (int j = 0; j < 4; j++) bb[j] = Bs[k][tx*4+j];
            #pragma unroll
            for (int i = 0; i < 4; i++)
                #pragma unroll
                for (int j = 0; j < 4; j++) acc[i][j] += a[i]*bb[j];
        }
        __syncthreads();
    }
    #pragma unroll
    for (int i = 0; i < 4; i++) {
        int m = mBase + ty*4 + i;
        #pragma unroll
        for (int j = 0; j < 4; j++) {
            int c = nBase + tx*4 + j;
            int dim = c & 255;
            int ri = c >> 8;           // 0 = real, 1 = imag
            out[((size_t)m*DIMM + dim)*2 + ri] = acc[i][j];
        }
    }
}

// ---------------- launch ------------------------------------------------------
extern "C" void kernel_launch(void* const* d_in, const int* in_sizes, int n_in,
                              void* d_out, int out_size) {
    const float* xr    = (const float*)d_in[0];
    const float* xi    = (const float*)d_in[1];
    const float* wq_r  = (const float*)d_in[2];
    const float* wq_i  = (const float*)d_in[3];
    const float* wkv_r = (const float*)d_in[4];
    const float* wkv_i = (const float*)d_in[5];
    const float* wo_r  = (const float*)d_in[6];
    const float* wo_i  = (const float*)d_in[7];
    float* out = (float*)d_out;

    // opt into >48KB dynamic smem (idempotent; not a stream op, capture-safe)
    cudaFuncSetAttribute(attn_kernel, cudaFuncAttributeMaxDynamicSharedMemorySize,
                         (int)sizeof(AtSmem));

    pack_w1<<<(KK1*NN1 + 255)/256, 256>>>(wq_r, wq_i, wkv_r, wkv_i);
    pack_w2<<<(KK1*NN2 + 255)/256, 256>>>(wo_r, wo_i);
    gemm_qkv<<<dim3(NN1/64, M_TOT/64), 256>>>(xr, xi);
    attn_kernel<<<dim3(BSZ*HH, NSEQ/32), 256, sizeof(AtSmem)>>>();
    gemm_out<<<dim3(NN2/64, M_TOT/64), 256>>>(out);
}

// round 6
// speedup vs baseline: 3.0031x; 3.0031x over previous
#include <cuda_runtime.h>
#include <cuda_fp16.h>
#include <cstdint>

#define BSZ 2
#define NSEQ 2048
#define DIMM 256
#define HH 8
#define DHD 32
#define M_TOT (BSZ*NSEQ)
#define KK1 512
#define NN1 1536
#define NN2 512

// ---------------- scratch ------------------------------------------------------
__device__ __align__(16) float g_W1[KK1*NN1];
__device__ __align__(16) float g_W2[KK1*NN2];
__device__ __align__(16) __half g_Qrh[16*2048*32], g_Qrl[16*2048*32];
__device__ __align__(16) __half g_Qih[16*2048*32], g_Qil[16*2048*32];
__device__ __align__(16) __half g_Krh[16*2048*32], g_Krl[16*2048*32];
__device__ __align__(16) __half g_Kih[16*2048*32], g_Kil[16*2048*32];
__device__ __align__(16) __half g_VTh[16*64*2048];          // [bh][d(vr0-31|vi32-63)][n]
__device__ __align__(16) float g_Mr[M_TOT*DIMM];
__device__ __align__(16) float g_Mi[M_TOT*DIMM];

// ---------------- PTX helpers --------------------------------------------------
__device__ __forceinline__ uint32_t smem_u32(const void* p) {
    uint32_t a;
    asm("{ .reg .u64 t; cvta.to.shared.u64 t, %1; cvt.u32.u64 %0, t; }" : "=r"(a) : "l"(p));
    return a;
}
__device__ __forceinline__ void cp16(uint32_t dst, const void* src) {
    asm volatile("cp.async.cg.shared.global [%0], [%1], 16;" :: "r"(dst), "l"(src));
}
#define CP_COMMIT() asm volatile("cp.async.commit_group;" ::: "memory")
#define CP_WAIT0()  asm volatile("cp.async.wait_group 0;" ::: "memory")

__device__ __forceinline__ void ldm4(uint32_t* r, uint32_t addr) {
    asm volatile("ldmatrix.sync.aligned.m8n8.x4.shared.b16 {%0,%1,%2,%3}, [%4];"
        : "=r"(r[0]), "=r"(r[1]), "=r"(r[2]), "=r"(r[3]) : "r"(addr));
}
__device__ __forceinline__ void mma16816(float* d, const uint32_t* a, const uint32_t* b) {
    asm volatile("mma.sync.aligned.m16n8k16.row.col.f32.f16.f16.f32 "
        "{%0,%1,%2,%3}, {%4,%5,%6,%7}, {%8,%9}, {%0,%1,%2,%3};"
        : "+f"(d[0]), "+f"(d[1]), "+f"(d[2]), "+f"(d[3])
        : "r"(a[0]), "r"(a[1]), "r"(a[2]), "r"(a[3]), "r"(b[0]), "r"(b[1]));
}
__device__ __forceinline__ float ex2(float x) {
    float r; asm("ex2.approx.f32 %0, %1;" : "=f"(r) : "f"(x)); return r;
}
__device__ __forceinline__ uint32_t pk(float a, float b) {
    __half2 h = __floats2half2_rn(a, b);
    return *reinterpret_cast<uint32_t*>(&h);
}

// ---------------- weight packing -----------------------------------------------
__global__ void pack_w1(const float* __restrict__ wq_r, const float* __restrict__ wq_i,
                        const float* __restrict__ wkv_r, const float* __restrict__ wkv_i) {
    int idx = blockIdx.x*blockDim.x + threadIdx.x;
    if (idx >= KK1*NN1) return;
    int k = idx / NN1, c = idx % NN1;
    int reg = c >> 8, cc = c & 255;
    bool top = (k < 256);
    int kr = k & 255;
    float v;
    switch (reg) {
        case 0: v = top ? wq_r[kr*256+cc]      : -wq_i[kr*256+cc];      break;
        case 1: v = top ? wq_i[kr*256+cc]      :  wq_r[kr*256+cc];      break;
        case 2: v = top ? wkv_r[kr*512+cc]     : -wkv_i[kr*512+cc];     break;
        case 3: v = top ? wkv_i[kr*512+cc]     :  wkv_r[kr*512+cc];     break;
        case 4: v = top ? wkv_r[kr*512+256+cc] : -wkv_i[kr*512+256+cc]; break;
        default:v = top ? wkv_i[kr*512+256+cc] :  wkv_r[kr*512+256+cc]; break;
    }
    g_W1[idx] = v;
}
__global__ void pack_w2(const float* __restrict__ wo_r, const float* __restrict__ wo_i) {
    int idx = blockIdx.x*blockDim.x + threadIdx.x;
    if (idx >= KK1*NN2) return;
    int k = idx / NN2, c = idx % NN2;
    bool top = (k < 256);
    int kr = k & 255, co = c & 255;
    float v;
    if (c < 256) v = top ? wo_r[kr*256+co] : -wo_i[kr*256+co];
    else         v = top ? wo_i[kr*256+co] :  wo_r[kr*256+co];
    g_W2[idx] = v;
}

// ---------------- GEMM 1: X @ W1 -> fp16 hi/lo split QKV ------------------------
__global__ void gemm_qkv(const float* __restrict__ xr, const float* __restrict__ xi) {
    __shared__ __align__(16) float As[16][64];
    __shared__ __align__(16) float Bs[16][64];
    int tid = threadIdx.x;
    int tx = tid & 15, ty = tid >> 4;
    int mBase = blockIdx.y * 64, nBase = blockIdx.x * 64;
    float acc[4][4] = {};
    for (int kt = 0; kt < KK1; kt += 16) {
        {
            int lin = tid * 4;
            int ar = lin >> 4, ak = lin & 15;
            int gm = mBase + ar, gk = kt + ak;
            const float* src = (gk < 256) ? (xr + (size_t)gm*256 + gk)
                                          : (xi + (size_t)gm*256 + gk - 256);
            float4 v = *(const float4*)src;
            As[ak+0][ar] = v.x; As[ak+1][ar] = v.y; As[ak+2][ar] = v.z; As[ak+3][ar] = v.w;
        }
        {
            int lin = tid * 4;
            int bk = lin >> 6, bc = lin & 63;
            *(float4*)&Bs[bk][bc] = *(const float4*)&g_W1[(size_t)(kt+bk)*NN1 + nBase + bc];
        }
        __syncthreads();
        #pragma unroll
        for (int k = 0; k < 16; k++) {
            float a[4], bb[4];
            #pragma unroll
            for (int i = 0; i < 4; i++) a[i] = As[k][ty*4+i];
            #pragma unroll
            for (int j = 0; j < 4; j++) bb[j] = Bs[k][tx*4+j];
            #pragma unroll
            for (int i = 0; i < 4; i++)
                #pragma unroll
                for (int j = 0; j < 4; j++) acc[i][j] += a[i]*bb[j];
        }
        __syncthreads();
    }
    #pragma unroll
    for (int i = 0; i < 4; i++) {
        int m = mBase + ty*4 + i;
        int b = m >> 11, n = m & 2047;
        #pragma unroll
        for (int j = 0; j < 4; j++) {
            int c = nBase + tx*4 + j;
            int reg = c >> 8, rem = c & 255;
            int hd = rem >> 5, d = rem & 31;
            int bhq = b*HH + hd;
            float v = acc[i][j];
            __half hi = __float2half_rn(v);
            if (reg < 4) {
                __half lo = __float2half_rn(v - __half2float(hi));
                size_t off = ((size_t)bhq*2048 + n)*32 + d;
                switch (reg) {
                    case 0: g_Qrh[off] = hi; g_Qrl[off] = lo; break;
                    case 1: g_Qih[off] = hi; g_Qil[off] = lo; break;
                    case 2: g_Krh[off] = hi; g_Krl[off] = lo; break;
                    default:g_Kih[off] = hi; g_Kil[off] = lo; break;
                }
            } else {
                g_VTh[((size_t)bhq*64 + (reg-4)*32 + d)*2048 + n] = hi;
            }
        }
    }
}

// ---------------- HMMA attention -------------------------------------------------
// smem: QH [128][40]h @0 (10240) | QL @10240 | slots @20480: s*29696:
//       K2H [128][40]h +0 | K2L +10240 | VT [64][72]h +20480 (9216)
#define SLOT 29696
#define SM_TOTAL (20480 + 2*SLOT)

__global__ void __launch_bounds__(256, 1) attn_mma() {
    extern __shared__ __align__(16) unsigned char sm[];
    const int tid = threadIdx.x, w = tid >> 5, lane = tid & 31;
    const int bh = blockIdx.x;
    const int row0 = blockIdx.y * 64;
    const uint32_t smb = smem_u32(sm);
    const int r8 = lane & 7, q = lane >> 3;

    auto prefetch = [&](int t) {
        int ct = t * 64;
        uint32_t so = smb + 20480 + (uint32_t)(t & 1) * SLOT;
        #pragma unroll
        for (int i = 0; i < 2; i++) {
            int c = tid + (i << 8);
            int row = c >> 2, pc = c & 3;
            size_t soff = ((size_t)bh*2048 + ct + (row & 63))*32 + pc*8;
            const __half* sh = (row < 64) ? g_Krh : g_Kih;
            const __half* sl = (row < 64) ? g_Krl : g_Kil;
            cp16(so + row*80 + pc*16, sh + soff);
            cp16(so + 10240 + row*80 + pc*16, sl + soff);
        }
        #pragma unroll
        for (int i = 0; i < 2; i++) {
            int c = tid + (i << 8);
            int dd = c >> 3, pc = c & 7;
            cp16(so + 20480 + dd*144 + pc*16,
                 g_VTh + ((size_t)bh*64 + dd)*2048 + ct + pc*8);
        }
    };

    prefetch(0); CP_COMMIT();

    // load Q (hi/lo) into smem
    #pragma unroll
    for (int i = 0; i < 2; i++) {
        int c = tid + (i << 8);
        int row = c >> 2, pc = c & 3;
        size_t soff = ((size_t)bh*2048 + row0 + (row & 63))*32 + pc*8;
        const __half* sh = (row < 64) ? g_Qrh : g_Qih;
        const __half* sl = (row < 64) ? g_Qrl : g_Qil;
        *(uint4*)(sm + row*80 + pc*16) = *(const uint4*)(sh + soff);
        *(uint4*)(sm + 10240 + row*80 + pc*16) = *(const uint4*)(sl + soff);
    }
    CP_WAIT0();
    __syncthreads();

    // Q fragments (persist whole loop). Warp strip rows m0..m0+15.
    const int m0 = 16 * w;
    uint32_t aqh[2][4], aql[2][4];
    #pragma unroll
    for (int ks = 0; ks < 2; ks++) {
        uint32_t ad = smb + (uint32_t)(m0 + r8 + (q & 1)*8)*80 + ks*32 + (q >> 1)*16;
        ldm4(aqh[ks], ad);
        ldm4(aql[ks], ad + 10240);
    }

    float X[8][4] = {};   // P(cols 0-63)  x V  strip 16x64
    float Y[8][4] = {};   // P(cols 64-127)x V
    float l00 = 0.f, l01 = 0.f, l10 = 0.f, l11 = 0.f;  // [row rr][half h]
    const float C = (float)(1.4426950408889634 / 5.656854249492380);
    const float SHIFT = 10.0f;   // exp2-domain shift: keeps unnormalized P in fp16 range

    for (int t = 0; t < 32; t++) {
        uint32_t so = smb + 20480 + (uint32_t)(t & 1) * SLOT;
        if (t < 31) { prefetch(t + 1); CP_COMMIT(); }

        // ---- S = Q2 K2^T (hi/lo split: hh + hl + lh) ----
        float S[16][4];
        #pragma unroll
        for (int nb = 0; nb < 16; nb++)
            #pragma unroll
            for (int e = 0; e < 4; e++) S[nb][e] = 0.f;

        #pragma unroll
        for (int nbp = 0; nbp < 8; nbp++) {
            #pragma unroll
            for (int ks = 0; ks < 2; ks++) {
                uint32_t ad = so + (uint32_t)(nbp*16 + r8 + (q >> 1)*8)*80 + ks*32 + (q & 1)*16;
                uint32_t bh4[4], bl4[4];
                ldm4(bh4, ad);
                ldm4(bl4, ad + 10240);
                mma16816(S[2*nbp],   aqh[ks], bh4);
                mma16816(S[2*nbp+1], aqh[ks], bh4+2);
                mma16816(S[2*nbp],   aqh[ks], bl4);
                mma16816(S[2*nbp+1], aqh[ks], bl4+2);
                mma16816(S[2*nbp],   aql[ks], bh4);
                mma16816(S[2*nbp+1], aql[ks], bh4+2);
            }
        }

        // ---- exp2 (shifted) + row-sum + pack into PV A-fragments ----
        uint32_t Pf[2][4][4];
        #pragma unroll
        for (int h2 = 0; h2 < 2; h2++) {
            float ls0 = 0.f, ls1 = 0.f;
            #pragma unroll
            for (int ks = 0; ks < 4; ks++) {
                int nb = 8*h2 + 2*ks;
                float p00 = ex2(fmaf(S[nb][0],   C, -SHIFT));
                float p01 = ex2(fmaf(S[nb][1],   C, -SHIFT));
                float p02 = ex2(fmaf(S[nb][2],   C, -SHIFT));
                float p03 = ex2(fmaf(S[nb][3],   C, -SHIFT));
                float p10 = ex2(fmaf(S[nb+1][0], C, -SHIFT));
                float p11 = ex2(fmaf(S[nb+1][1], C, -SHIFT));
                float p12 = ex2(fmaf(S[nb+1][2], C, -SHIFT));
                float p13 = ex2(fmaf(S[nb+1][3], C, -SHIFT));
                ls0 += p00 + p01 + p10 + p11;
                ls1 += p02 + p03 + p12 + p13;
                Pf[h2][ks][0] = pk(p00, p01);
                Pf[h2][ks][1] = pk(p02, p03);
                Pf[h2][ks][2] = pk(p10, p11);
                Pf[h2][ks][3] = pk(p12, p13);
            }
            if (h2 == 0) { l00 += ls0; l10 += ls1; }
            else         { l01 += ls0; l11 += ls1; }
        }

        // ---- O += P V ----
        uint32_t vt = so + 20480;
        #pragma unroll
        for (int dbp = 0; dbp < 4; dbp++) {
            #pragma unroll
            for (int ks = 0; ks < 4; ks++) {
                uint32_t ad = vt + (uint32_t)(dbp*16 + r8 + (q >> 1)*8)*144 + ks*32 + (q & 1)*16;
                uint32_t bv[4];
                ldm4(bv, ad);
                mma16816(X[2*dbp],   Pf[0][ks], bv);
                mma16816(X[2*dbp+1], Pf[0][ks], bv+2);
                mma16816(Y[2*dbp],   Pf[1][ks], bv);
                mma16816(Y[2*dbp+1], Pf[1][ks], bv+2);
            }
        }

        if (t < 31) { CP_WAIT0(); __syncthreads(); }
    }
    __syncthreads();

    // ---- normalize + sign-recombine ----
    l00 += __shfl_xor_sync(~0u, l00, 1); l00 += __shfl_xor_sync(~0u, l00, 2);
    l01 += __shfl_xor_sync(~0u, l01, 1); l01 += __shfl_xor_sync(~0u, l01, 2);
    l10 += __shfl_xor_sync(~0u, l10, 1); l10 += __shfl_xor_sync(~0u, l10, 2);
    l11 += __shfl_xor_sync(~0u, l11, 1); l11 += __shfl_xor_sync(~0u, l11, 2);
    float rl[2][2] = {{1.f/l00, 1.f/l01}, {1.f/l10, 1.f/l11}};

    float* orS = (float*)sm;             // [2][64][32]
    float* oiS = (float*)(sm + 16384);
    int grp = w >> 2;                    // 0 = qr rows, 1 = qi rows
    int mb = 16*(w & 3) + (lane >> 2);
    int dq = 2*(lane & 3);
    #pragma unroll
    for (int db = 0; db < 4; db++) {
        #pragma unroll
        for (int rr = 0; rr < 2; rr++) {
            #pragma unroll
            for (int dd = 0; dd < 2; dd++) {
                float x  = X[db][2*rr+dd]   * rl[rr][0];
                float x2 = X[db+4][2*rr+dd] * rl[rr][0];
                float y  = Y[db][2*rr+dd]   * rl[rr][1];
                float y2 = Y[db+4][2*rr+dd] * rl[rr][1];
                float orv = grp ? (-x2 - y) : (x - y2);
                float oiv = grp ? (x - y2)  : (x2 + y);
                int m = mb + rr*8, dcol = 8*db + dq + dd;
                orS[grp*2048 + m*32 + dcol] = orv;
                oiS[grp*2048 + m*32 + dcol] = oiv;
            }
        }
    }
    __syncthreads();
    {
        int b = bh >> 3, hh = bh & 7;
        for (int e = tid; e < 2048; e += 256) {
            int m = e >> 5, dcol = e & 31;
            float r  = orS[m*32 + dcol] + orS[2048 + m*32 + dcol];
            float im = oiS[m*32 + dcol] + oiS[2048 + m*32 + dcol];
            size_t o = ((size_t)(b*2048 + row0 + m))*256 + hh*32 + dcol;
            g_Mr[o] = r; g_Mi[o] = im;
        }
    }
}

// ---------------- GEMM 2 -----------------------------------------------------------
__global__ void gemm_out(float* __restrict__ out) {
    __shared__ __align__(16) float As[16][64];
    __shared__ __align__(16) float Bs[16][64];
    int tid = threadIdx.x;
    int tx = tid & 15, ty = tid >> 4;
    int mBase = blockIdx.y * 64, nBase = blockIdx.x * 64;
    float acc[4][4] = {};
    for (int kt = 0; kt < KK1; kt += 16) {
        {
            int lin = tid * 4;
            int ar = lin >> 4, ak = lin & 15;
            int gm = mBase + ar, gk = kt + ak;
            const float* src = (gk < 256) ? (g_Mr + (size_t)gm*256 + gk)
                                          : (g_Mi + (size_t)gm*256 + gk - 256);
            float4 v = *(const float4*)src;
            As[ak+0][ar] = v.x; As[ak+1][ar] = v.y; As[ak+2][ar] = v.z; As[ak+3][ar] = v.w;
        }
        {
            int lin = tid * 4;
            int bk = lin >> 6, bc = lin & 63;
            *(float4*)&Bs[bk][bc] = *(const float4*)&g_W2[(size_t)(kt+bk)*NN2 + nBase + bc];
        }
        __syncthreads();
        #pragma unroll
        for (int k = 0; k < 16; k++) {
            float a[4], bb[4];
            #pragma unroll
            for (int i = 0; i < 4; i++) a[i] = As[k][ty*4+i];
            #pragma unroll
            for (int j = 0; j < 4; j++) bb[j] = Bs[k][tx*4+j];
            #pragma unroll
            for (int i = 0; i < 4; i++)
                #pragma unroll
                for (int j = 0; j < 4; j++) acc[i][j] += a[i]*bb[j];
        }
        __syncthreads();
    }
    #pragma unroll
    for (int i = 0; i < 4; i++) {
        int m = mBase + ty*4 + i;
        #pragma unroll
        for (int j = 0; j < 4; j++) {
            int c = nBase + tx*4 + j;
            out[((size_t)m*DIMM + (c & 255))*2 + (c >> 8)] = acc[i][j];
        }
    }
}

// ---------------- launch -------------------------------------------------------------
extern "C" void kernel_launch(void* const* d_in, const int* in_sizes, int n_in,
                              void* d_out, int out_size) {
    const float* xr    = (const float*)d_in[0];
    const float* xi    = (const float*)d_in[1];
    const float* wq_r  = (const float*)d_in[2];
    const float* wq_i  = (const float*)d_in[3];
    const float* wkv_r = (const float*)d_in[4];
    const float* wkv_i = (const float*)d_in[5];
    const float* wo_r  = (const float*)d_in[6];
    const float* wo_i  = (const float*)d_in[7];
    float* out = (float*)d_out;

    cudaFuncSetAttribute(attn_mma, cudaFuncAttributeMaxDynamicSharedMemorySize, SM_TOTAL);

    pack_w1<<<(KK1*NN1 + 255)/256, 256>>>(wq_r, wq_i, wkv_r, wkv_i);
    pack_w2<<<(KK1*NN2 + 255)/256, 256>>>(wo_r, wo_i);
    gemm_qkv<<<dim3(NN1/64, M_TOT/64), 256>>>(xr, xi);
    attn_mma<<<dim3(16, 32), 256, SM_TOTAL>>>();
    gemm_out<<<dim3(NN2/64, M_TOT/64), 256>>>(out);
}

// round 7
// speedup vs baseline: 3.1325x; 1.0431x over previous
#include <cuda_runtime.h>
#include <cuda_fp16.h>
#include <cstdint>

#define BSZ 2
#define NSEQ 2048
#define DIMM 256
#define HH 8
#define DHD 32
#define M_TOT (BSZ*NSEQ)
#define KK1 512
#define NN1 1536
#define NN2 512

// ---------------- scratch ------------------------------------------------------
__device__ __align__(16) float g_W1[KK1*NN1];
__device__ __align__(16) float g_W2[KK1*NN2];
__device__ __align__(16) __half g_Qrh[16*2048*32], g_Qrl[16*2048*32];
__device__ __align__(16) __half g_Qih[16*2048*32], g_Qil[16*2048*32];
__device__ __align__(16) __half g_Krh[16*2048*32], g_Krl[16*2048*32];
__device__ __align__(16) __half g_Kih[16*2048*32], g_Kil[16*2048*32];
__device__ __align__(16) __half g_VTh[16*64*2048];          // [bh][d(vr0-31|vi32-63)][n]
__device__ __align__(16) float g_Mr[M_TOT*DIMM];
__device__ __align__(16) float g_Mi[M_TOT*DIMM];

// ---------------- PTX helpers --------------------------------------------------
__device__ __forceinline__ uint32_t smem_u32(const void* p) {
    uint32_t a;
    asm("{ .reg .u64 t; cvta.to.shared.u64 t, %1; cvt.u32.u64 %0, t; }" : "=r"(a) : "l"(p));
    return a;
}
__device__ __forceinline__ void cp16(uint32_t dst, const void* src) {
    asm volatile("cp.async.cg.shared.global [%0], [%1], 16;" :: "r"(dst), "l"(src));
}
#define CP_COMMIT() asm volatile("cp.async.commit_group;" ::: "memory")
#define CP_WAIT0()  asm volatile("cp.async.wait_group 0;" ::: "memory")

__device__ __forceinline__ void ldm4(uint32_t* r, uint32_t addr) {
    asm volatile("ldmatrix.sync.aligned.m8n8.x4.shared.b16 {%0,%1,%2,%3}, [%4];"
        : "=r"(r[0]), "=r"(r[1]), "=r"(r[2]), "=r"(r[3]) : "r"(addr));
}
__device__ __forceinline__ void mma16816(float* d, const uint32_t* a, const uint32_t* b) {
    asm volatile("mma.sync.aligned.m16n8k16.row.col.f32.f16.f16.f32 "
        "{%0,%1,%2,%3}, {%4,%5,%6,%7}, {%8,%9}, {%0,%1,%2,%3};"
        : "+f"(d[0]), "+f"(d[1]), "+f"(d[2]), "+f"(d[3])
        : "r"(a[0]), "r"(a[1]), "r"(a[2]), "r"(a[3]), "r"(b[0]), "r"(b[1]));
}
__device__ __forceinline__ float ex2(float x) {
    float r; asm("ex2.approx.f32 %0, %1;" : "=f"(r) : "f"(x)); return r;
}
__device__ __forceinline__ uint32_t pk(float a, float b) {
    __half2 h = __floats2half2_rn(a, b);
    return *reinterpret_cast<uint32_t*>(&h);
}

// ---------------- weight packing -----------------------------------------------
__global__ void pack_w1(const float* __restrict__ wq_r, const float* __restrict__ wq_i,
                        const float* __restrict__ wkv_r, const float* __restrict__ wkv_i) {
    int idx = blockIdx.x*blockDim.x + threadIdx.x;
    if (idx >= KK1*NN1) return;
    int k = idx / NN1, c = idx % NN1;
    int reg = c >> 8, cc = c & 255;
    bool top = (k < 256);
    int kr = k & 255;
    float v;
    switch (reg) {
        case 0: v = top ? wq_r[kr*256+cc]      : -wq_i[kr*256+cc];      break;
        case 1: v = top ? wq_i[kr*256+cc]      :  wq_r[kr*256+cc];      break;
        case 2: v = top ? wkv_r[kr*512+cc]     : -wkv_i[kr*512+cc];     break;
        case 3: v = top ? wkv_i[kr*512+cc]     :  wkv_r[kr*512+cc];     break;
        case 4: v = top ? wkv_r[kr*512+256+cc] : -wkv_i[kr*512+256+cc]; break;
        default:v = top ? wkv_i[kr*512+256+cc] :  wkv_r[kr*512+256+cc]; break;
    }
    g_W1[idx] = v;
}
__global__ void pack_w2(const float* __restrict__ wo_r, const float* __restrict__ wo_i) {
    int idx = blockIdx.x*blockDim.x + threadIdx.x;
    if (idx >= KK1*NN2) return;
    int k = idx / NN2, c = idx % NN2;
    bool top = (k < 256);
    int kr = k & 255, co = c & 255;
    float v;
    if (c < 256) v = top ? wo_r[kr*256+co] : -wo_i[kr*256+co];
    else         v = top ? wo_i[kr*256+co] :  wo_r[kr*256+co];
    g_W2[idx] = v;
}

// ---------------- GEMM 1: X @ W1 -> fp16 hi/lo split QKV ------------------------
__global__ void gemm_qkv(const float* __restrict__ xr, const float* __restrict__ xi) {
    __shared__ __align__(16) float As[16][64];
    __shared__ __align__(16) float Bs[16][64];
    int tid = threadIdx.x;
    int tx = tid & 15, ty = tid >> 4;
    int mBase = blockIdx.y * 64, nBase = blockIdx.x * 64;
    float acc[4][4] = {};
    for (int kt = 0; kt < KK1; kt += 16) {
        {
            int lin = tid * 4;
            int ar = lin >> 4, ak = lin & 15;
            int gm = mBase + ar, gk = kt + ak;
            const float* src = (gk < 256) ? (xr + (size_t)gm*256 + gk)
                                          : (xi + (size_t)gm*256 + gk - 256);
            float4 v = *(const float4*)src;
            As[ak+0][ar] = v.x; As[ak+1][ar] = v.y; As[ak+2][ar] = v.z; As[ak+3][ar] = v.w;
        }
        {
            int lin = tid * 4;
            int bk = lin >> 6, bc = lin & 63;
            *(float4*)&Bs[bk][bc] = *(const float4*)&g_W1[(size_t)(kt+bk)*NN1 + nBase + bc];
        }
        __syncthreads();
        #pragma unroll
        for (int k = 0; k < 16; k++) {
            float a[4], bb[4];
            #pragma unroll
            for (int i = 0; i < 4; i++) a[i] = As[k][ty*4+i];
            #pragma unroll
            for (int j = 0; j < 4; j++) bb[j] = Bs[k][tx*4+j];
            #pragma unroll
            for (int i = 0; i < 4; i++)
                #pragma unroll
                for (int j = 0; j < 4; j++) acc[i][j] += a[i]*bb[j];
        }
        __syncthreads();
    }
    #pragma unroll
    for (int i = 0; i < 4; i++) {
        int m = mBase + ty*4 + i;
        int b = m >> 11, n = m & 2047;
        #pragma unroll
        for (int j = 0; j < 4; j++) {
            int c = nBase + tx*4 + j;
            int reg = c >> 8, rem = c & 255;
            int hd = rem >> 5, d = rem & 31;
            int bhq = b*HH + hd;
            float v = acc[i][j];
            __half hi = __float2half_rn(v);
            if (reg < 4) {
                __half lo = __float2half_rn(v - __half2float(hi));
                size_t off = ((size_t)bhq*2048 + n)*32 + d;
                switch (reg) {
                    case 0: g_Qrh[off] = hi; g_Qrl[off] = lo; break;
                    case 1: g_Qih[off] = hi; g_Qil[off] = lo; break;
                    case 2: g_Krh[off] = hi; g_Krl[off] = lo; break;
                    default:g_Kih[off] = hi; g_Kil[off] = lo; break;
                }
            } else {
                g_VTh[((size_t)bhq*64 + (reg-4)*32 + d)*2048 + n] = hi;
            }
        }
    }
}

// ---------------- HMMA attention -------------------------------------------------
// 128 threads, 32-query tile, 2 CTAs/SM. smem: 2 slots of 29696:
//   K2H [128][40]h +0 | K2L +10240 | VT [64][72]h +20480 (9216)
#define SLOT 29696
#define SM_TOTAL (2*SLOT)

__global__ void __launch_bounds__(128, 2) attn_mma() {
    extern __shared__ __align__(16) unsigned char sm[];
    const int tid = threadIdx.x, w = tid >> 5, lane = tid & 31;
    const int bh = blockIdx.x;
    const int row0 = blockIdx.y * 32;
    const uint32_t smb = smem_u32(sm);
    const int r8 = lane & 7, q = lane >> 3;

    auto prefetch = [&](int t) {
        int ct = t * 64;
        uint32_t so = smb + (uint32_t)(t & 1) * SLOT;
        #pragma unroll
        for (int i = 0; i < 4; i++) {
            int c = tid + (i << 7);
            int row = c >> 2, pc = c & 3;
            size_t soff = ((size_t)bh*2048 + ct + (row & 63))*32 + pc*8;
            const __half* sh = (row < 64) ? g_Krh : g_Kih;
            const __half* sl = (row < 64) ? g_Krl : g_Kil;
            cp16(so + row*80 + pc*16, sh + soff);
            cp16(so + 10240 + row*80 + pc*16, sl + soff);
        }
        #pragma unroll
        for (int i = 0; i < 4; i++) {
            int c = tid + (i << 7);
            int dd = c >> 3, pc = c & 7;
            cp16(so + 20480 + dd*144 + pc*16,
                 g_VTh + ((size_t)bh*64 + dd)*2048 + ct + pc*8);
        }
    };

    prefetch(0); CP_COMMIT();

    // Q fragments: direct gmem load per m16n8k16 A-fragment layout.
    // Stacked M rows 0-31 = qr (warps 0,1), 32-63 = qi (warps 2,3); strip = 16 rows.
    const __half* Qh = (w < 2) ? g_Qrh : g_Qih;
    const __half* Ql = (w < 2) ? g_Qrl : g_Qil;
    size_t qoff = ((size_t)bh*2048 + row0 + (w & 1)*16 + (lane >> 2))*32 + (lane & 3)*2;
    uint32_t aqh[2][4], aql[2][4];
    #pragma unroll
    for (int ks = 0; ks < 2; ks++) {
        aqh[ks][0] = *(const uint32_t*)(Qh + qoff + ks*16);
        aqh[ks][1] = *(const uint32_t*)(Qh + qoff + 256 + ks*16);
        aqh[ks][2] = *(const uint32_t*)(Qh + qoff + ks*16 + 8);
        aqh[ks][3] = *(const uint32_t*)(Qh + qoff + 256 + ks*16 + 8);
        aql[ks][0] = *(const uint32_t*)(Ql + qoff + ks*16);
        aql[ks][1] = *(const uint32_t*)(Ql + qoff + 256 + ks*16);
        aql[ks][2] = *(const uint32_t*)(Ql + qoff + ks*16 + 8);
        aql[ks][3] = *(const uint32_t*)(Ql + qoff + 256 + ks*16 + 8);
    }
    CP_WAIT0();
    __syncthreads();

    float X[8][4] = {};   // P(cols 0-63)  x V  strip 16x64
    float Y[8][4] = {};   // P(cols 64-127)x V
    float l00 = 0.f, l01 = 0.f, l10 = 0.f, l11 = 0.f;  // [row rr][half h]
    const float C = (float)(1.4426950408889634 / 5.656854249492380);
    const float SHIFT = 10.0f;   // exp2-domain shift keeps unnormalized P in fp16 range

    for (int t = 0; t < 32; t++) {
        uint32_t so = smb + (uint32_t)(t & 1) * SLOT;
        if (t < 31) { prefetch(t + 1); CP_COMMIT(); }

        // ---- S = Q2 K2^T (hi/lo split: hh + hl + lh) ----
        float S[16][4];
        #pragma unroll
        for (int nb = 0; nb < 16; nb++)
            #pragma unroll
            for (int e = 0; e < 4; e++) S[nb][e] = 0.f;

        #pragma unroll
        for (int nbp = 0; nbp < 8; nbp++) {
            #pragma unroll
            for (int ks = 0; ks < 2; ks++) {
                uint32_t ad = so + (uint32_t)(nbp*16 + r8 + (q >> 1)*8)*80 + ks*32 + (q & 1)*16;
                uint32_t bh4[4], bl4[4];
                ldm4(bh4, ad);
                ldm4(bl4, ad + 10240);
                mma16816(S[2*nbp],   aqh[ks], bh4);
                mma16816(S[2*nbp+1], aqh[ks], bh4+2);
                mma16816(S[2*nbp],   aqh[ks], bl4);
                mma16816(S[2*nbp+1], aqh[ks], bl4+2);
                mma16816(S[2*nbp],   aql[ks], bh4);
                mma16816(S[2*nbp+1], aql[ks], bh4+2);
            }
        }

        // ---- exp2 (shifted) + row-sum + pack into PV A-fragments ----
        uint32_t Pf[2][4][4];
        #pragma unroll
        for (int h2 = 0; h2 < 2; h2++) {
            float ls0 = 0.f, ls1 = 0.f;
            #pragma unroll
            for (int ks = 0; ks < 4; ks++) {
                int nb = 8*h2 + 2*ks;
                float p00 = ex2(fmaf(S[nb][0],   C, -SHIFT));
                float p01 = ex2(fmaf(S[nb][1],   C, -SHIFT));
                float p02 = ex2(fmaf(S[nb][2],   C, -SHIFT));
                float p03 = ex2(fmaf(S[nb][3],   C, -SHIFT));
                float p10 = ex2(fmaf(S[nb+1][0], C, -SHIFT));
                float p11 = ex2(fmaf(S[nb+1][1], C, -SHIFT));
                float p12 = ex2(fmaf(S[nb+1][2], C, -SHIFT));
                float p13 = ex2(fmaf(S[nb+1][3], C, -SHIFT));
                ls0 += p00 + p01 + p10 + p11;
                ls1 += p02 + p03 + p12 + p13;
                Pf[h2][ks][0] = pk(p00, p01);
                Pf[h2][ks][1] = pk(p02, p03);
                Pf[h2][ks][2] = pk(p10, p11);
                Pf[h2][ks][3] = pk(p12, p13);
            }
            if (h2 == 0) { l00 += ls0; l10 += ls1; }
            else         { l01 += ls0; l11 += ls1; }
        }

        // ---- O += P V ----
        uint32_t vt = so + 20480;
        #pragma unroll
        for (int dbp = 0; dbp < 4; dbp++) {
            #pragma unroll
            for (int ks = 0; ks < 4; ks++) {
                uint32_t ad = vt + (uint32_t)(dbp*16 + r8 + (q >> 1)*8)*144 + ks*32 + (q & 1)*16;
                uint32_t bv[4];
                ldm4(bv, ad);
                mma16816(X[2*dbp],   Pf[0][ks], bv);
                mma16816(X[2*dbp+1], Pf[0][ks], bv+2);
                mma16816(Y[2*dbp],   Pf[1][ks], bv);
                mma16816(Y[2*dbp+1], Pf[1][ks], bv+2);
            }
        }

        if (t < 31) { CP_WAIT0(); __syncthreads(); }
    }
    __syncthreads();

    // ---- normalize + sign-recombine ----
    l00 += __shfl_xor_sync(~0u, l00, 1); l00 += __shfl_xor_sync(~0u, l00, 2);
    l01 += __shfl_xor_sync(~0u, l01, 1); l01 += __shfl_xor_sync(~0u, l01, 2);
    l10 += __shfl_xor_sync(~0u, l10, 1); l10 += __shfl_xor_sync(~0u, l10, 2);
    l11 += __shfl_xor_sync(~0u, l11, 1); l11 += __shfl_xor_sync(~0u, l11, 2);
    float rl[2][2] = {{1.f/l00, 1.f/l01}, {1.f/l10, 1.f/l11}};

    float* orS = (float*)sm;             // [2][32][32]
    float* oiS = (float*)(sm + 8192);
    int grp = w >> 1;                    // 0 = qr rows, 1 = qi rows
    int mb = 16*(w & 1) + (lane >> 2);
    int dq = 2*(lane & 3);
    #pragma unroll
    for (int db = 0; db < 4; db++) {
        #pragma unroll
        for (int rr = 0; rr < 2; rr++) {
            #pragma unroll
            for (int dd = 0; dd < 2; dd++) {
                float x  = X[db][2*rr+dd]   * rl[rr][0];
                float x2 = X[db+4][2*rr+dd] * rl[rr][0];
                float y  = Y[db][2*rr+dd]   * rl[rr][1];
                float y2 = Y[db+4][2*rr+dd] * rl[rr][1];
                float orv = grp ? (-x2 - y) : (x - y2);
                float oiv = grp ? (x - y2)  : (x2 + y);
                int m = mb + rr*8, dcol = 8*db + dq + dd;
                orS[grp*1024 + m*32 + dcol] = orv;
                oiS[grp*1024 + m*32 + dcol] = oiv;
            }
        }
    }
    __syncthreads();
    {
        int b = bh >> 3, hh = bh & 7;
        for (int e = tid; e < 1024; e += 128) {
            int m = e >> 5, dcol = e & 31;
            float r  = orS[m*32 + dcol] + orS[1024 + m*32 + dcol];
            float im = oiS[m*32 + dcol] + oiS[1024 + m*32 + dcol];
            size_t o = ((size_t)(b*2048 + row0 + m))*256 + hh*32 + dcol;
            g_Mr[o] = r; g_Mi[o] = im;
        }
    }
}

// ---------------- GEMM 2 -----------------------------------------------------------
__global__ void gemm_out(float* __restrict__ out) {
    __shared__ __align__(16) float As[16][64];
    __shared__ __align__(16) float Bs[16][64];
    int tid = threadIdx.x;
    int tx = tid & 15, ty = tid >> 4;
    int mBase = blockIdx.y * 64, nBase = blockIdx.x * 64;
    float acc[4][4] = {};
    for (int kt = 0; kt < KK1; kt += 16) {
        {
            int lin = tid * 4;
            int ar = lin >> 4, ak = lin & 15;
            int gm = mBase + ar, gk = kt + ak;
            const float* src = (gk < 256) ? (g_Mr + (size_t)gm*256 + gk)
                                          : (g_Mi + (size_t)gm*256 + gk - 256);
            float4 v = *(const float4*)src;
            As[ak+0][ar] = v.x; As[ak+1][ar] = v.y; As[ak+2][ar] = v.z; As[ak+3][ar] = v.w;
        }
        {
            int lin = tid * 4;
            int bk = lin >> 6, bc = lin & 63;
            *(float4*)&Bs[bk][bc] = *(const float4*)&g_W2[(size_t)(kt+bk)*NN2 + nBase + bc];
        }
        __syncthreads();
        #pragma unroll
        for (int k = 0; k < 16; k++) {
            float a[4], bb[4];
            #pragma unroll
            for (int i = 0; i < 4; i++) a[i] = As[k][ty*4+i];
            #pragma unroll
            for (int j = 0; j < 4; j++) bb[j] = Bs[k][tx*4+j];
            #pragma unroll
            for (int i = 0; i < 4; i++)
                #pragma unroll
                for (int j = 0; j < 4; j++) acc[i][j] += a[i]*bb[j];
        }
        __syncthreads();
    }
    #pragma unroll
    for (int i = 0; i < 4; i++) {
        int m = mBase + ty*4 + i;
        #pragma unroll
        for (int j = 0; j < 4; j++) {
            int c = nBase + tx*4 + j;
            out[((size_t)m*DIMM + (c & 255))*2 + (c >> 8)] = acc[i][j];
        }
    }
}

// ---------------- launch -------------------------------------------------------------
extern "C" void kernel_launch(void* const* d_in, const int* in_sizes, int n_in,
                              void* d_out, int out_size) {
    const float* xr    = (const float*)d_in[0];
    const float* xi    = (const float*)d_in[1];
    const float* wq_r  = (const float*)d_in[2];
    const float* wq_i  = (const float*)d_in[3];
    const float* wkv_r = (const float*)d_in[4];
    const float* wkv_i = (const float*)d_in[5];
    const float* wo_r  = (const float*)d_in[6];
    const float* wo_i  = (const float*)d_in[7];
    float* out = (float*)d_out;

    cudaFuncSetAttribute(attn_mma, cudaFuncAttributeMaxDynamicSharedMemorySize, SM_TOTAL);

    pack_w1<<<(KK1*NN1 + 255)/256, 256>>>(wq_r, wq_i, wkv_r, wkv_i);
    pack_w2<<<(KK1*NN2 + 255)/256, 256>>>(wo_r, wo_i);
    gemm_qkv<<<dim3(NN1/64, M_TOT/64), 256>>>(xr, xi);
    attn_mma<<<dim3(16, 64), 128, SM_TOTAL>>>();
    gemm_out<<<dim3(NN2/64, M_TOT/64), 256>>>(out);
}

// round 10
// speedup vs baseline: 4.0695x; 1.2991x over previous
#include <cuda_runtime.h>
#include <cuda_fp16.h>
#include <cstdint>

#define BSZ 2
#define NSEQ 2048
#define DIMM 256
#define HH 8
#define DHD 32
#define M_TOT (BSZ*NSEQ)
#define KK1 512
#define NN1 1536
#define NN2 512

// ---------------- scratch ------------------------------------------------------
__device__ __align__(16) __half g_Xh[M_TOT*KK1];
__device__ __align__(16) __half g_Xl[M_TOT*KK1];
__device__ __align__(16) __half g_W1th[NN1*KK1];
__device__ __align__(16) __half g_W1tl[NN1*KK1];
__device__ __align__(16) float  g_W2[KK1*NN2];
__device__ __align__(16) __half g_Qrh[16*2048*32], g_Qrl[16*2048*32];
__device__ __align__(16) __half g_Qih[16*2048*32], g_Qil[16*2048*32];
__device__ __align__(16) __half g_Krh[16*2048*32], g_Krl[16*2048*32];
__device__ __align__(16) __half g_Kih[16*2048*32], g_Kil[16*2048*32];
__device__ __align__(16) __half g_VTh[16*64*2048];          // [bh][d(vr|vi)][n]
__device__ __align__(16) float  g_Mr[M_TOT*DIMM];
__device__ __align__(16) float  g_Mi[M_TOT*DIMM];

// ---------------- PTX helpers --------------------------------------------------
__device__ __forceinline__ uint32_t smem_u32(const void* p) {
    uint32_t a;
    asm("{ .reg .u64 t; cvta.to.shared.u64 t, %1; cvt.u32.u64 %0, t; }" : "=r"(a) : "l"(p));
    return a;
}
__device__ __forceinline__ void cp16(uint32_t dst, const void* src) {
    asm volatile("cp.async.cg.shared.global [%0], [%1], 16;" :: "r"(dst), "l"(src));
}
#define CP_COMMIT() asm volatile("cp.async.commit_group;" ::: "memory")
#define CP_WAIT0()  asm volatile("cp.async.wait_group 0;" ::: "memory")

__device__ __forceinline__ void ldm4(uint32_t* r, uint32_t addr) {
    asm volatile("ldmatrix.sync.aligned.m8n8.x4.shared.b16 {%0,%1,%2,%3}, [%4];"
        : "=r"(r[0]), "=r"(r[1]), "=r"(r[2]), "=r"(r[3]) : "r"(addr));
}
__device__ __forceinline__ void mma16816(float* d, const uint32_t* a, const uint32_t* b) {
    asm volatile("mma.sync.aligned.m16n8k16.row.col.f32.f16.f16.f32 "
        "{%0,%1,%2,%3}, {%4,%5,%6,%7}, {%8,%9}, {%0,%1,%2,%3};"
        : "+f"(d[0]), "+f"(d[1]), "+f"(d[2]), "+f"(d[3])
        : "r"(a[0]), "r"(a[1]), "r"(a[2]), "r"(a[3]), "r"(b[0]), "r"(b[1]));
}
__device__ __forceinline__ float ex2(float x) {
    float r; asm("ex2.approx.f32 %0, %1;" : "=f"(r) : "f"(x)); return r;
}
__device__ __forceinline__ uint32_t pk(float a, float b) {
    __half2 h = __floats2half2_rn(a, b);
    return *reinterpret_cast<uint32_t*>(&h);
}

// ---------------- input / weight packing ----------------------------------------
__global__ void xsplit(const float* __restrict__ xr, const float* __restrict__ xi) {
    int idx = blockIdx.x*blockDim.x + threadIdx.x;
    if (idx >= M_TOT*KK1) return;
    int m = idx >> 9, k = idx & 511;
    float v = (k < 256) ? xr[m*256 + k] : xi[m*256 + k - 256];
    __half hi = __float2half_rn(v);
    g_Xh[idx] = hi;
    g_Xl[idx] = __float2half_rn(v - __half2float(hi));
}
__global__ void pack_w1t(const float* __restrict__ wq_r, const float* __restrict__ wq_i,
                         const float* __restrict__ wkv_r, const float* __restrict__ wkv_i) {
    int idx = blockIdx.x*blockDim.x + threadIdx.x;
    if (idx >= NN1*KK1) return;
    int c = idx >> 9, k = idx & 511;
    int reg = c >> 8, cc = c & 255;
    bool top = (k < 256);
    int kr = k & 255;
    float v;
    switch (reg) {
        case 0: v = top ? wq_r[kr*256+cc]      : -wq_i[kr*256+cc];      break;
        case 1: v = top ? wq_i[kr*256+cc]      :  wq_r[kr*256+cc];      break;
        case 2: v = top ? wkv_r[kr*512+cc]     : -wkv_i[kr*512+cc];     break;
        case 3: v = top ? wkv_i[kr*512+cc]     :  wkv_r[kr*512+cc];     break;
        case 4: v = top ? wkv_r[kr*512+256+cc] : -wkv_i[kr*512+256+cc]; break;
        default:v = top ? wkv_i[kr*512+256+cc] :  wkv_r[kr*512+256+cc]; break;
    }
    __half hi = __float2half_rn(v);
    g_W1th[idx] = hi;
    g_W1tl[idx] = __float2half_rn(v - __half2float(hi));
}
__global__ void pack_w2(const float* __restrict__ wo_r, const float* __restrict__ wo_i) {
    int idx = blockIdx.x*blockDim.x + threadIdx.x;
    if (idx >= KK1*NN2) return;
    int k = idx / NN2, c = idx % NN2;
    bool top = (k < 256);
    int kr = k & 255, co = c & 255;
    float v;
    if (c < 256) v = top ? wo_r[kr*256+co] : -wo_i[kr*256+co];
    else         v = top ? wo_i[kr*256+co] :  wo_r[kr*256+co];
    g_W2[idx] = v;
}

// ---------------- HMMA QKV GEMM (fp32 via fp16 hi/lo 3-pass) --------------------
// 256 thr, tile M=64 x N=64, K=512 in k32 chunks, double-buffered static smem.
#define GSTG 20480

__global__ void __launch_bounds__(256, 2) gemm_qkv_mma() {
    __shared__ __align__(16) unsigned char sm[2*GSTG];
    const int tid = threadIdx.x, w = tid >> 5, lane = tid & 31;
    const int wm = w & 3, wn = w >> 2;
    const int mBase = blockIdx.y * 64, nBase = blockIdx.x * 64;
    const uint32_t smb = smem_u32(sm);
    const int r8 = lane & 7, q = lane >> 3;

    auto prefetch = [&](int t) {
        int k0 = t * 32;
        uint32_t so = smb + (uint32_t)(t & 1) * GSTG;
        int row = tid >> 2, seg = tid & 3;
        size_t ga = (size_t)(mBase + row)*512 + k0 + seg*8;
        cp16(so + row*80 + seg*16, g_Xh + ga);
        cp16(so + 5120 + row*80 + seg*16, g_Xl + ga);
        size_t gb = (size_t)(nBase + row)*512 + k0 + seg*8;
        cp16(so + 10240 + row*80 + seg*16, g_W1th + gb);
        cp16(so + 15360 + row*80 + seg*16, g_W1tl + gb);
    };

    prefetch(0); CP_COMMIT();
    CP_WAIT0();
    __syncthreads();

    float Xc[4][4] = {};

    for (int t = 0; t < 16; t++) {
        uint32_t so = smb + (uint32_t)(t & 1) * GSTG;
        if (t < 15) { prefetch(t + 1); CP_COMMIT(); }

        uint32_t ah[2][4], al[2][4];
        #pragma unroll
        for (int ks = 0; ks < 2; ks++) {
            uint32_t ad = so + (uint32_t)(16*wm + r8 + (q & 1)*8)*80 + ks*32 + (q >> 1)*16;
            ldm4(ah[ks], ad);
            ldm4(al[ks], ad + 5120);
        }
        #pragma unroll
        for (int nbp = 0; nbp < 2; nbp++) {
            #pragma unroll
            for (int ks = 0; ks < 2; ks++) {
                uint32_t ad = so + 10240
                            + (uint32_t)(wn*32 + nbp*16 + r8 + (q >> 1)*8)*80 + ks*32 + (q & 1)*16;
                uint32_t bh4[4], bl4[4];
                ldm4(bh4, ad);
                ldm4(bl4, ad + 5120);
                mma16816(Xc[2*nbp],   ah[ks], bh4);
                mma16816(Xc[2*nbp+1], ah[ks], bh4+2);
                mma16816(Xc[2*nbp],   ah[ks], bl4);
                mma16816(Xc[2*nbp+1], ah[ks], bl4+2);
                mma16816(Xc[2*nbp],   al[ks], bh4);
                mma16816(Xc[2*nbp+1], al[ks], bh4+2);
            }
        }
        if (t < 15) { CP_WAIT0(); __syncthreads(); }
    }

    // ---- epilogue: scatter into Q/K hi-lo + transposed V ----
    #pragma unroll
    for (int nf = 0; nf < 4; nf++) {
        #pragma unroll
        for (int e = 0; e < 4; e++) {
            int m = mBase + 16*wm + (e >> 1)*8 + (lane >> 2);
            int c = nBase + wn*32 + nf*8 + (lane & 3)*2 + (e & 1);
            float v = Xc[nf][e];
            int reg = c >> 8, rem = c & 255;
            int hd = rem >> 5, d = rem & 31;
            int b = m >> 11, n = m & 2047;
            int bhq = b*HH + hd;
            __half hi = __float2half_rn(v);
            if (reg < 4) {
                __half lo = __float2half_rn(v - __half2float(hi));
                size_t off = ((size_t)bhq*2048 + n)*32 + d;
                switch (reg) {
                    case 0: g_Qrh[off] = hi; g_Qrl[off] = lo; break;
                    case 1: g_Qih[off] = hi; g_Qil[off] = lo; break;
                    case 2: g_Krh[off] = hi; g_Krl[off] = lo; break;
                    default:g_Kih[off] = hi; g_Kil[off] = lo; break;
                }
            } else {
                g_VTh[((size_t)bhq*64 + (reg-4)*32 + d)*2048 + n] = hi;
            }
        }
    }
}

// ---------------- HMMA attention (round-7 verbatim) ------------------------------
#define SLOT 29696
#define SM_TOTAL (2*SLOT)

__global__ void __launch_bounds__(128, 2) attn_mma() {
    extern __shared__ __align__(16) unsigned char sm[];
    const int tid = threadIdx.x, w = tid >> 5, lane = tid & 31;
    const int bh = blockIdx.x;
    const int row0 = blockIdx.y * 32;
    const uint32_t smb = smem_u32(sm);
    const int r8 = lane & 7, q = lane >> 3;

    auto prefetch = [&](int t) {
        int ct = t * 64;
        uint32_t so = smb + (uint32_t)(t & 1) * SLOT;
        #pragma unroll
        for (int i = 0; i < 4; i++) {
            int c = tid + (i << 7);
            int row = c >> 2, pc = c & 3;
            size_t soff = ((size_t)bh*2048 + ct + (row & 63))*32 + pc*8;
            const __half* sh = (row < 64) ? g_Krh : g_Kih;
            const __half* sl = (row < 64) ? g_Krl : g_Kil;
            cp16(so + row*80 + pc*16, sh + soff);
            cp16(so + 10240 + row*80 + pc*16, sl + soff);
        }
        #pragma unroll
        for (int i = 0; i < 4; i++) {
            int c = tid + (i << 7);
            int dd = c >> 3, pc = c & 7;
            cp16(so + 20480 + dd*144 + pc*16,
                 g_VTh + ((size_t)bh*64 + dd)*2048 + ct + pc*8);
        }
    };

    prefetch(0); CP_COMMIT();

    const __half* Qh = (w < 2) ? g_Qrh : g_Qih;
    const __half* Ql = (w < 2) ? g_Qrl : g_Qil;
    size_t qoff = ((size_t)bh*2048 + row0 + (w & 1)*16 + (lane >> 2))*32 + (lane & 3)*2;
    uint32_t aqh[2][4], aql[2][4];
    #pragma unroll
    for (int ks = 0; ks < 2; ks++) {
        aqh[ks][0] = *(const uint32_t*)(Qh + qoff + ks*16);
        aqh[ks][1] = *(const uint32_t*)(Qh + qoff + 256 + ks*16);
        aqh[ks][2] = *(const uint32_t*)(Qh + qoff + ks*16 + 8);
        aqh[ks][3] = *(const uint32_t*)(Qh + qoff + 256 + ks*16 + 8);
        aql[ks][0] = *(const uint32_t*)(Ql + qoff + ks*16);
        aql[ks][1] = *(const uint32_t*)(Ql + qoff + 256 + ks*16);
        aql[ks][2] = *(const uint32_t*)(Ql + qoff + ks*16 + 8);
        aql[ks][3] = *(const uint32_t*)(Ql + qoff + 256 + ks*16 + 8);
    }
    CP_WAIT0();
    __syncthreads();

    float X[8][4] = {};
    float Y[8][4] = {};
    float l00 = 0.f, l01 = 0.f, l10 = 0.f, l11 = 0.f;
    const float C = (float)(1.4426950408889634 / 5.656854249492380);
    const float SHIFT = 10.0f;

    for (int t = 0; t < 32; t++) {
        uint32_t so = smb + (uint32_t)(t & 1) * SLOT;
        if (t < 31) { prefetch(t + 1); CP_COMMIT(); }

        float S[16][4];
        #pragma unroll
        for (int nb = 0; nb < 16; nb++)
            #pragma unroll
            for (int e = 0; e < 4; e++) S[nb][e] = 0.f;

        #pragma unroll
        for (int nbp = 0; nbp < 8; nbp++) {
            #pragma unroll
            for (int ks = 0; ks < 2; ks++) {
                uint32_t ad = so + (uint32_t)(nbp*16 + r8 + (q >> 1)*8)*80 + ks*32 + (q & 1)*16;
                uint32_t bh4[4], bl4[4];
                ldm4(bh4, ad);
                ldm4(bl4, ad + 10240);
                mma16816(S[2*nbp],   aqh[ks], bh4);
                mma16816(S[2*nbp+1], aqh[ks], bh4+2);
                mma16816(S[2*nbp],   aqh[ks], bl4);
                mma16816(S[2*nbp+1], aqh[ks], bl4+2);
                mma16816(S[2*nbp],   aql[ks], bh4);
                mma16816(S[2*nbp+1], aql[ks], bh4+2);
            }
        }

        uint32_t Pf[2][4][4];
        #pragma unroll
        for (int h2 = 0; h2 < 2; h2++) {
            float ls0 = 0.f, ls1 = 0.f;
            #pragma unroll
            for (int ks = 0; ks < 4; ks++) {
                int nb = 8*h2 + 2*ks;
                float p00 = ex2(fmaf(S[nb][0],   C, -SHIFT));
                float p01 = ex2(fmaf(S[nb][1],   C, -SHIFT));
                float p02 = ex2(fmaf(S[nb][2],   C, -SHIFT));
                float p03 = ex2(fmaf(S[nb][3],   C, -SHIFT));
                float p10 = ex2(fmaf(S[nb+1][0], C, -SHIFT));
                float p11 = ex2(fmaf(S[nb+1][1], C, -SHIFT));
                float p12 = ex2(fmaf(S[nb+1][2], C, -SHIFT));
                float p13 = ex2(fmaf(S[nb+1][3], C, -SHIFT));
                ls0 += p00 + p01 + p10 + p11;
                ls1 += p02 + p03 + p12 + p13;
                Pf[h2][ks][0] = pk(p00, p01);
                Pf[h2][ks][1] = pk(p02, p03);
                Pf[h2][ks][2] = pk(p10, p11);
                Pf[h2][ks][3] = pk(p12, p13);
            }
            if (h2 == 0) { l00 += ls0; l10 += ls1; }
            else         { l01 += ls0; l11 += ls1; }
        }

        uint32_t vt = so + 20480;
        #pragma unroll
        for (int dbp = 0; dbp < 4; dbp++) {
            #pragma unroll
            for (int ks = 0; ks < 4; ks++) {
                uint32_t ad = vt + (uint32_t)(dbp*16 + r8 + (q >> 1)*8)*144 + ks*32 + (q & 1)*16;
                uint32_t bv[4];
                ldm4(bv, ad);
                mma16816(X[2*dbp],   Pf[0][ks], bv);
                mma16816(X[2*dbp+1], Pf[0][ks], bv+2);
                mma16816(Y[2*dbp],   Pf[1][ks], bv);
                mma16816(Y[2*dbp+1], Pf[1][ks], bv+2);
            }
        }

        if (t < 31) { CP_WAIT0(); __syncthreads(); }
    }
    __syncthreads();

    l00 += __shfl_xor_sync(~0u, l00, 1); l00 += __shfl_xor_sync(~0u, l00, 2);
    l01 += __shfl_xor_sync(~0u, l01, 1); l01 += __shfl_xor_sync(~0u, l01, 2);
    l10 += __shfl_xor_sync(~0u, l10, 1); l10 += __shfl_xor_sync(~0u, l10, 2);
    l11 += __shfl_xor_sync(~0u, l11, 1); l11 += __shfl_xor_sync(~0u, l11, 2);
    float rl[2][2] = {{1.f/l00, 1.f/l01}, {1.f/l10, 1.f/l11}};

    float* orS = (float*)sm;             // [2][32][32]
    float* oiS = (float*)(sm + 8192);
    int grp = w >> 1;
    int mb = 16*(w & 1) + (lane >> 2);
    int dq = 2*(lane & 3);
    #pragma unroll
    for (int db = 0; db < 4; db++) {
        #pragma unroll
        for (int rr = 0; rr < 2; rr++) {
            #pragma unroll
            for (int dd = 0; dd < 2; dd++) {
                float x  = X[db][2*rr+dd]   * rl[rr][0];
                float x2 = X[db+4][2*rr+dd] * rl[rr][0];
                float y  = Y[db][2*rr+dd]   * rl[rr][1];
                float y2 = Y[db+4][2*rr+dd] * rl[rr][1];
                float orv = grp ? (-x2 - y) : (x - y2);
                float oiv = grp ? (x - y2)  : (x2 + y);
                int m = mb + rr*8, dcol = 8*db + dq + dd;
                orS[grp*1024 + m*32 + dcol] = orv;
                oiS[grp*1024 + m*32 + dcol] = oiv;
            }
        }
    }
    __syncthreads();
    {
        int b = bh >> 3, hh = bh & 7;
        for (int e = tid; e < 1024; e += 128) {
            int m = e >> 5, dcol = e & 31;
            float r  = orS[m*32 + dcol] + orS[1024 + m*32 + dcol];
            float im = oiS[m*32 + dcol] + oiS[1024 + m*32 + dcol];
            size_t o = ((size_t)(b*2048 + row0 + m))*256 + hh*32 + dcol;
            g_Mr[o] = r; g_Mi[o] = im;
        }
    }
}

// ---------------- GEMM 2 (round-7 scalar, verbatim) -------------------------------
__global__ void gemm_out(float* __restrict__ out) {
    __shared__ __align__(16) float As[16][64];
    __shared__ __align__(16) float Bs[16][64];
    int tid = threadIdx.x;
    int tx = tid & 15, ty = tid >> 4;
    int mBase = blockIdx.y * 64, nBase = blockIdx.x * 64;
    float acc[4][4] = {};
    for (int kt = 0; kt < KK1; kt += 16) {
        {
            int lin = tid * 4;
            int ar = lin >> 4, ak = lin & 15;
            int gm = mBase + ar, gk = kt + ak;
            const float* src = (gk < 256) ? (g_Mr + (size_t)gm*256 + gk)
                                          : (g_Mi + (size_t)gm*256 + gk - 256);
            float4 v = *(const float4*)src;
            As[ak+0][ar] = v.x; As[ak+1][ar] = v.y; As[ak+2][ar] = v.z; As[ak+3][ar] = v.w;
        }
        {
            int lin = tid * 4;
            int bk = lin >> 6, bc = lin & 63;
            *(float4*)&Bs[bk][bc] = *(const float4*)&g_W2[(size_t)(kt+bk)*NN2 + nBase + bc];
        }
        __syncthreads();
        #pragma unroll
        for (int k = 0; k < 16; k++) {
            float a[4], bb[4];
            #pragma unroll
            for (int i = 0; i < 4; i++) a[i] = As[k][ty*4+i];
            #pragma unroll
            for (int j = 0; j < 4; j++) bb[j] = Bs[k][tx*4+j];
            #pragma unroll
            for (int i = 0; i < 4; i++)
                #pragma unroll
                for (int j = 0; j < 4; j++) acc[i][j] += a[i]*bb[j];
        }
        __syncthreads();
    }
    #pragma unroll
    for (int i = 0; i < 4; i++) {
        int m = mBase + ty*4 + i;
        #pragma unroll
        for (int j = 0; j < 4; j++) {
            int c = nBase + tx*4 + j;
            out[((size_t)m*DIMM + (c & 255))*2 + (c >> 8)] = acc[i][j];
        }
    }
}

// ---------------- launch -------------------------------------------------------------
extern "C" void kernel_launch(void* const* d_in, const int* in_sizes, int n_in,
                              void* d_out, int out_size) {
    const float* xr    = (const float*)d_in[0];
    const float* xi    = (const float*)d_in[1];
    const float* wq_r  = (const float*)d_in[2];
    const float* wq_i  = (const float*)d_in[3];
    const float* wkv_r = (const float*)d_in[4];
    const float* wkv_i = (const float*)d_in[5];
    const float* wo_r  = (const float*)d_in[6];
    const float* wo_i  = (const float*)d_in[7];
    float* out = (float*)d_out;

    cudaFuncSetAttribute(attn_mma, cudaFuncAttributeMaxDynamicSharedMemorySize, SM_TOTAL);

    xsplit<<<(M_TOT*KK1 + 255)/256, 256>>>(xr, xi);
    pack_w1t<<<(NN1*KK1 + 255)/256, 256>>>(wq_r, wq_i, wkv_r, wkv_i);
    pack_w2<<<(KK1*NN2 + 255)/256, 256>>>(wo_r, wo_i);
    gemm_qkv_mma<<<dim3(NN1/64, M_TOT/64), 256>>>();
    attn_mma<<<dim3(16, 64), 128, SM_TOTAL>>>();
    gemm_out<<<dim3(NN2/64, M_TOT/64), 256>>>(out);
}

// round 11
// speedup vs baseline: 4.6374x; 1.1396x over previous
#include <cuda_runtime.h>
#include <cuda_fp16.h>
#include <cstdint>

#define BSZ 2
#define NSEQ 2048
#define DIMM 256
#define HH 8
#define DHD 32
#define M_TOT (BSZ*NSEQ)
#define KK1 512
#define NN1 1536
#define NN2 512

// ---------------- scratch ------------------------------------------------------
__device__ __align__(16) __half g_Xh[M_TOT*KK1];
__device__ __align__(16) __half g_Xl[M_TOT*KK1];
__device__ __align__(16) __half g_W1th[NN1*KK1];
__device__ __align__(16) __half g_W1tl[NN1*KK1];
__device__ __align__(16) __half g_W2th[NN2*KK1];
__device__ __align__(16) __half g_W2tl[NN2*KK1];
__device__ __align__(16) __half g_Qrh[16*2048*32], g_Qrl[16*2048*32];
__device__ __align__(16) __half g_Qih[16*2048*32], g_Qil[16*2048*32];
__device__ __align__(16) __half g_Krh[16*2048*32], g_Krl[16*2048*32];
__device__ __align__(16) __half g_Kih[16*2048*32], g_Kil[16*2048*32];
__device__ __align__(16) __half g_VTh[16*64*2048];          // [bh][d(vr|vi)][n]
__device__ __align__(16) __half g_Mh[M_TOT*KK1];            // [4096][512] (Mr|Mi) hi
__device__ __align__(16) __half g_Ml[M_TOT*KK1];            // lo

// ---------------- PTX helpers --------------------------------------------------
__device__ __forceinline__ uint32_t smem_u32(const void* p) {
    uint32_t a;
    asm("{ .reg .u64 t; cvta.to.shared.u64 t, %1; cvt.u32.u64 %0, t; }" : "=r"(a) : "l"(p));
    return a;
}
__device__ __forceinline__ void cp16(uint32_t dst, const void* src) {
    asm volatile("cp.async.cg.shared.global [%0], [%1], 16;" :: "r"(dst), "l"(src));
}
#define CP_COMMIT() asm volatile("cp.async.commit_group;" ::: "memory")
#define CP_WAIT0()  asm volatile("cp.async.wait_group 0;" ::: "memory")

__device__ __forceinline__ void ldm4(uint32_t* r, uint32_t addr) {
    asm volatile("ldmatrix.sync.aligned.m8n8.x4.shared.b16 {%0,%1,%2,%3}, [%4];"
        : "=r"(r[0]), "=r"(r[1]), "=r"(r[2]), "=r"(r[3]) : "r"(addr));
}
__device__ __forceinline__ void mma16816(float* d, const uint32_t* a, const uint32_t* b) {
    asm volatile("mma.sync.aligned.m16n8k16.row.col.f32.f16.f16.f32 "
        "{%0,%1,%2,%3}, {%4,%5,%6,%7}, {%8,%9}, {%0,%1,%2,%3};"
        : "+f"(d[0]), "+f"(d[1]), "+f"(d[2]), "+f"(d[3])
        : "r"(a[0]), "r"(a[1]), "r"(a[2]), "r"(a[3]), "r"(b[0]), "r"(b[1]));
}
__device__ __forceinline__ float ex2(float x) {
    float r; asm("ex2.approx.f32 %0, %1;" : "=f"(r) : "f"(x)); return r;
}
__device__ __forceinline__ uint32_t pk(float a, float b) {
    __half2 h = __floats2half2_rn(a, b);
    return *reinterpret_cast<uint32_t*>(&h);
}

// ---------------- input / weight packing ----------------------------------------
__global__ void xsplit(const float* __restrict__ xr, const float* __restrict__ xi) {
    int idx = blockIdx.x*blockDim.x + threadIdx.x;
    if (idx >= M_TOT*KK1) return;
    int m = idx >> 9, k = idx & 511;
    float v = (k < 256) ? xr[m*256 + k] : xi[m*256 + k - 256];
    __half hi = __float2half_rn(v);
    g_Xh[idx] = hi;
    g_Xl[idx] = __float2half_rn(v - __half2float(hi));
}
__global__ void pack_w1t(const float* __restrict__ wq_r, const float* __restrict__ wq_i,
                         const float* __restrict__ wkv_r, const float* __restrict__ wkv_i) {
    int idx = blockIdx.x*blockDim.x + threadIdx.x;
    if (idx >= NN1*KK1) return;
    int c = idx >> 9, k = idx & 511;
    int reg = c >> 8, cc = c & 255;
    bool top = (k < 256);
    int kr = k & 255;
    float v;
    switch (reg) {
        case 0: v = top ? wq_r[kr*256+cc]      : -wq_i[kr*256+cc];      break;
        case 1: v = top ? wq_i[kr*256+cc]      :  wq_r[kr*256+cc];      break;
        case 2: v = top ? wkv_r[kr*512+cc]     : -wkv_i[kr*512+cc];     break;
        case 3: v = top ? wkv_i[kr*512+cc]     :  wkv_r[kr*512+cc];     break;
        case 4: v = top ? wkv_r[kr*512+256+cc] : -wkv_i[kr*512+256+cc]; break;
        default:v = top ? wkv_i[kr*512+256+cc] :  wkv_r[kr*512+256+cc]; break;
    }
    __half hi = __float2half_rn(v);
    g_W1th[idx] = hi;
    g_W1tl[idx] = __float2half_rn(v - __half2float(hi));
}
__global__ void pack_w2t(const float* __restrict__ wo_r, const float* __restrict__ wo_i) {
    int idx = blockIdx.x*blockDim.x + threadIdx.x;
    if (idx >= NN2*KK1) return;
    int c = idx >> 9, k = idx & 511;
    bool top = (k < 256);
    int kr = k & 255, co = c & 255;
    float v;
    if (c < 256) v = top ? wo_r[kr*256+co] : -wo_i[kr*256+co];
    else         v = top ? wo_i[kr*256+co] :  wo_r[kr*256+co];
    __half hi = __float2half_rn(v);
    g_W2th[idx] = hi;
    g_W2tl[idx] = __float2half_rn(v - __half2float(hi));
}

// ---------------- HMMA GEMM (fp32 via fp16 hi/lo 3-pass) ------------------------
// SEL=0: A=g_Xh/Xl, B=g_W1th/W1tl, epilogue scatters Q/K/V.   grid (24, 64)
// SEL=1: A=g_Mh/Ml,  B=g_W2th/W2tl, epilogue writes interleaved out. grid (8, 64)
// All global-array references are DEVICE-side (never passed as kernel args).
#define GSTG 20480

template<int SEL>
__global__ void __launch_bounds__(256, 2) gemm_mma(float* __restrict__ outp) {
    __shared__ __align__(16) unsigned char sm[2*GSTG];
    const int tid = threadIdx.x, w = tid >> 5, lane = tid & 31;
    const int wm = w & 3, wn = w >> 2;
    const int mBase = blockIdx.y * 64, nBase = blockIdx.x * 64;
    const uint32_t smb = smem_u32(sm);
    const int r8 = lane & 7, q = lane >> 3;

    const __half* Ah = SEL ? g_Mh : g_Xh;
    const __half* Al = SEL ? g_Ml : g_Xl;
    const __half* Bh = SEL ? g_W2th : g_W1th;
    const __half* Bl = SEL ? g_W2tl : g_W1tl;

    auto prefetch = [&](int t) {
        int k0 = t * 32;
        uint32_t so = smb + (uint32_t)(t & 1) * GSTG;
        int row = tid >> 2, seg = tid & 3;
        size_t ga = (size_t)(mBase + row)*512 + k0 + seg*8;
        cp16(so + row*80 + seg*16, Ah + ga);
        cp16(so + 5120 + row*80 + seg*16, Al + ga);
        size_t gb = (size_t)(nBase + row)*512 + k0 + seg*8;
        cp16(so + 10240 + row*80 + seg*16, Bh + gb);
        cp16(so + 15360 + row*80 + seg*16, Bl + gb);
    };

    prefetch(0); CP_COMMIT();
    CP_WAIT0();
    __syncthreads();

    float Xc[4][4] = {};

    for (int t = 0; t < 16; t++) {
        uint32_t so = smb + (uint32_t)(t & 1) * GSTG;
        if (t < 15) { prefetch(t + 1); CP_COMMIT(); }

        uint32_t ah[2][4], al[2][4];
        #pragma unroll
        for (int ks = 0; ks < 2; ks++) {
            uint32_t ad = so + (uint32_t)(16*wm + r8 + (q & 1)*8)*80 + ks*32 + (q >> 1)*16;
            ldm4(ah[ks], ad);
            ldm4(al[ks], ad + 5120);
        }
        #pragma unroll
        for (int nbp = 0; nbp < 2; nbp++) {
            #pragma unroll
            for (int ks = 0; ks < 2; ks++) {
                uint32_t ad = so + 10240
                            + (uint32_t)(wn*32 + nbp*16 + r8 + (q >> 1)*8)*80 + ks*32 + (q & 1)*16;
                uint32_t bh4[4], bl4[4];
                ldm4(bh4, ad);
                ldm4(bl4, ad + 5120);
                mma16816(Xc[2*nbp],   ah[ks], bh4);
                mma16816(Xc[2*nbp+1], ah[ks], bh4+2);
                mma16816(Xc[2*nbp],   ah[ks], bl4);
                mma16816(Xc[2*nbp+1], ah[ks], bl4+2);
                mma16816(Xc[2*nbp],   al[ks], bh4);
                mma16816(Xc[2*nbp+1], al[ks], bh4+2);
            }
        }
        if (t < 15) { CP_WAIT0(); __syncthreads(); }
    }

    // ---- epilogue ----
    #pragma unroll
    for (int nf = 0; nf < 4; nf++) {
        #pragma unroll
        for (int e = 0; e < 4; e++) {
            int m = mBase + 16*wm + (e >> 1)*8 + (lane >> 2);
            int c = nBase + wn*32 + nf*8 + (lane & 3)*2 + (e & 1);
            float v = Xc[nf][e];
            if (SEL == 0) {
                int reg = c >> 8, rem = c & 255;
                int hd = rem >> 5, d = rem & 31;
                int b = m >> 11, n = m & 2047;
                int bhq = b*HH + hd;
                __half hi = __float2half_rn(v);
                if (reg < 4) {
                    __half lo = __float2half_rn(v - __half2float(hi));
                    size_t off = ((size_t)bhq*2048 + n)*32 + d;
                    switch (reg) {
                        case 0: g_Qrh[off] = hi; g_Qrl[off] = lo; break;
                        case 1: g_Qih[off] = hi; g_Qil[off] = lo; break;
                        case 2: g_Krh[off] = hi; g_Krl[off] = lo; break;
                        default:g_Kih[off] = hi; g_Kil[off] = lo; break;
                    }
                } else {
                    g_VTh[((size_t)bhq*64 + (reg-4)*32 + d)*2048 + n] = hi;
                }
            } else {
                outp[((size_t)m*DIMM + (c & 255))*2 + (c >> 8)] = v;
            }
        }
    }
}

// ---------------- HMMA attention --------------------------------------------------
#define SLOT 29696
#define SM_TOTAL (2*SLOT)

__global__ void __launch_bounds__(128, 2) attn_mma() {
    extern __shared__ __align__(16) unsigned char sm[];
    const int tid = threadIdx.x, w = tid >> 5, lane = tid & 31;
    const int bh = blockIdx.x;
    const int row0 = blockIdx.y * 32;
    const uint32_t smb = smem_u32(sm);
    const int r8 = lane & 7, q = lane >> 3;

    auto prefetch = [&](int t) {
        int ct = t * 64;
        uint32_t so = smb + (uint32_t)(t & 1) * SLOT;
        #pragma unroll
        for (int i = 0; i < 4; i++) {
            int c = tid + (i << 7);
            int row = c >> 2, pc = c & 3;
            size_t soff = ((size_t)bh*2048 + ct + (row & 63))*32 + pc*8;
            const __half* sh = (row < 64) ? g_Krh : g_Kih;
            const __half* sl = (row < 64) ? g_Krl : g_Kil;
            cp16(so + row*80 + pc*16, sh + soff);
            cp16(so + 10240 + row*80 + pc*16, sl + soff);
        }
        #pragma unroll
        for (int i = 0; i < 4; i++) {
            int c = tid + (i << 7);
            int dd = c >> 3, pc = c & 7;
            cp16(so + 20480 + dd*144 + pc*16,
                 g_VTh + ((size_t)bh*64 + dd)*2048 + ct + pc*8);
        }
    };

    prefetch(0); CP_COMMIT();

    const __half* Qh = (w < 2) ? g_Qrh : g_Qih;
    const __half* Ql = (w < 2) ? g_Qrl : g_Qil;
    size_t qoff = ((size_t)bh*2048 + row0 + (w & 1)*16 + (lane >> 2))*32 + (lane & 3)*2;
    uint32_t aqh[2][4], aql[2][4];
    #pragma unroll
    for (int ks = 0; ks < 2; ks++) {
        aqh[ks][0] = *(const uint32_t*)(Qh + qoff + ks*16);
        aqh[ks][1] = *(const uint32_t*)(Qh + qoff + 256 + ks*16);
        aqh[ks][2] = *(const uint32_t*)(Qh + qoff + ks*16 + 8);
        aqh[ks][3] = *(const uint32_t*)(Qh + qoff + 256 + ks*16 + 8);
        aql[ks][0] = *(const uint32_t*)(Ql + qoff + ks*16);
        aql[ks][1] = *(const uint32_t*)(Ql + qoff + 256 + ks*16);
        aql[ks][2] = *(const uint32_t*)(Ql + qoff + ks*16 + 8);
        aql[ks][3] = *(const uint32_t*)(Ql + qoff + 256 + ks*16 + 8);
    }
    CP_WAIT0();
    __syncthreads();

    float X[8][4] = {};
    float Y[8][4] = {};
    float l00 = 0.f, l01 = 0.f, l10 = 0.f, l11 = 0.f;
    const float C = (float)(1.4426950408889634 / 5.656854249492380);
    const float SHIFT = 10.0f;

    for (int t = 0; t < 32; t++) {
        uint32_t so = smb + (uint32_t)(t & 1) * SLOT;
        if (t < 31) { prefetch(t + 1); CP_COMMIT(); }

        float S[16][4];
        #pragma unroll
        for (int nb = 0; nb < 16; nb++)
            #pragma unroll
            for (int e = 0; e < 4; e++) S[nb][e] = 0.f;

        #pragma unroll
        for (int nbp = 0; nbp < 8; nbp++) {
            #pragma unroll
            for (int ks = 0; ks < 2; ks++) {
                uint32_t ad = so + (uint32_t)(nbp*16 + r8 + (q >> 1)*8)*80 + ks*32 + (q & 1)*16;
                uint32_t bh4[4], bl4[4];
                ldm4(bh4, ad);
                ldm4(bl4, ad + 10240);
                mma16816(S[2*nbp],   aqh[ks], bh4);
                mma16816(S[2*nbp+1], aqh[ks], bh4+2);
                mma16816(S[2*nbp],   aqh[ks], bl4);
                mma16816(S[2*nbp+1], aqh[ks], bl4+2);
                mma16816(S[2*nbp],   aql[ks], bh4);
                mma16816(S[2*nbp+1], aql[ks], bh4+2);
            }
        }

        // exp + PV per column-half: PV(h0) tensor work overlaps exp(h1) MUFU work
        uint32_t vt = so + 20480;
        #pragma unroll
        for (int h2 = 0; h2 < 2; h2++) {
            uint32_t Pf[4][4];
            float ls0 = 0.f, ls1 = 0.f;
            #pragma unroll
            for (int ks = 0; ks < 4; ks++) {
                int nb = 8*h2 + 2*ks;
                float p00 = ex2(fmaf(S[nb][0],   C, -SHIFT));
                float p01 = ex2(fmaf(S[nb][1],   C, -SHIFT));
                float p02 = ex2(fmaf(S[nb][2],   C, -SHIFT));
                float p03 = ex2(fmaf(S[nb][3],   C, -SHIFT));
                float p10 = ex2(fmaf(S[nb+1][0], C, -SHIFT));
                float p11 = ex2(fmaf(S[nb+1][1], C, -SHIFT));
                float p12 = ex2(fmaf(S[nb+1][2], C, -SHIFT));
                float p13 = ex2(fmaf(S[nb+1][3], C, -SHIFT));
                ls0 += p00 + p01 + p10 + p11;
                ls1 += p02 + p03 + p12 + p13;
                Pf[ks][0] = pk(p00, p01);
                Pf[ks][1] = pk(p02, p03);
                Pf[ks][2] = pk(p10, p11);
                Pf[ks][3] = pk(p12, p13);
            }
            if (h2 == 0) { l00 += ls0; l10 += ls1; }
            else         { l01 += ls0; l11 += ls1; }

            float (*Z)[4] = h2 ? Y : X;
            #pragma unroll
            for (int dbp = 0; dbp < 4; dbp++) {
                #pragma unroll
                for (int ks = 0; ks < 4; ks++) {
                    uint32_t ad = vt + (uint32_t)(dbp*16 + r8 + (q >> 1)*8)*144 + ks*32 + (q & 1)*16;
                    uint32_t bv[4];
                    ldm4(bv, ad);
                    mma16816(Z[2*dbp],   Pf[ks], bv);
                    mma16816(Z[2*dbp+1], Pf[ks], bv+2);
                }
            }
        }

        if (t < 31) { CP_WAIT0(); __syncthreads(); }
    }
    __syncthreads();

    l00 += __shfl_xor_sync(~0u, l00, 1); l00 += __shfl_xor_sync(~0u, l00, 2);
    l01 += __shfl_xor_sync(~0u, l01, 1); l01 += __shfl_xor_sync(~0u, l01, 2);
    l10 += __shfl_xor_sync(~0u, l10, 1); l10 += __shfl_xor_sync(~0u, l10, 2);
    l11 += __shfl_xor_sync(~0u, l11, 1); l11 += __shfl_xor_sync(~0u, l11, 2);
    float rl[2][2] = {{1.f/l00, 1.f/l01}, {1.f/l10, 1.f/l11}};

    float* orS = (float*)sm;             // [2][32][32]
    float* oiS = (float*)(sm + 8192);
    int grp = w >> 1;
    int mb = 16*(w & 1) + (lane >> 2);
    int dq = 2*(lane & 3);
    #pragma unroll
    for (int db = 0; db < 4; db++) {
        #pragma unroll
        for (int rr = 0; rr < 2; rr++) {
            #pragma unroll
            for (int dd = 0; dd < 2; dd++) {
                float x  = X[db][2*rr+dd]   * rl[rr][0];
                float x2 = X[db+4][2*rr+dd] * rl[rr][0];
                float y  = Y[db][2*rr+dd]   * rl[rr][1];
                float y2 = Y[db+4][2*rr+dd] * rl[rr][1];
                float orv = grp ? (-x2 - y) : (x - y2);
                float oiv = grp ? (x - y2)  : (x2 + y);
                int m = mb + rr*8, dcol = 8*db + dq + dd;
                orS[grp*1024 + m*32 + dcol] = orv;
                oiS[grp*1024 + m*32 + dcol] = oiv;
            }
        }
    }
    __syncthreads();
    {
        int b = bh >> 3, hh = bh & 7;
        for (int e = tid; e < 1024; e += 128) {
            int m = e >> 5, dcol = e & 31;
            float r  = orS[m*32 + dcol] + orS[1024 + m*32 + dcol];
            float im = oiS[m*32 + dcol] + oiS[1024 + m*32 + dcol];
            size_t o = ((size_t)(b*2048 + row0 + m))*512 + hh*32 + dcol;
            __half rh = __float2half_rn(r);
            __half ih = __float2half_rn(im);
            g_Mh[o]       = rh;
            g_Ml[o]       = __float2half_rn(r - __half2float(rh));
            g_Mh[o + 256] = ih;
            g_Ml[o + 256] = __float2half_rn(im - __half2float(ih));
        }
    }
}

// ---------------- launch -------------------------------------------------------------
extern "C" void kernel_launch(void* const* d_in, const int* in_sizes, int n_in,
                              void* d_out, int out_size) {
    const float* xr    = (const float*)d_in[0];
    const float* xi    = (const float*)d_in[1];
    const float* wq_r  = (const float*)d_in[2];
    const float* wq_i  = (const float*)d_in[3];
    const float* wkv_r = (const float*)d_in[4];
    const float* wkv_i = (const float*)d_in[5];
    const float* wo_r  = (const float*)d_in[6];
    const float* wo_i  = (const float*)d_in[7];
    float* out = (float*)d_out;

    cudaFuncSetAttribute(attn_mma, cudaFuncAttributeMaxDynamicSharedMemorySize, SM_TOTAL);

    xsplit<<<(M_TOT*KK1 + 255)/256, 256>>>(xr, xi);
    pack_w1t<<<(NN1*KK1 + 255)/256, 256>>>(wq_r, wq_i, wkv_r, wkv_i);
    pack_w2t<<<(NN2*KK1 + 255)/256, 256>>>(wo_r, wo_i);
    gemm_mma<0><<<dim3(NN1/64, M_TOT/64), 256>>>(nullptr);
    attn_mma<<<dim3(16, 64), 128, SM_TOTAL>>>();
    gemm_mma<1><<<dim3(NN2/64, M_TOT/64), 256>>>(out);
}